// round 13
// baseline (speedup 1.0000x reference)
#include <cuda_runtime.h>
#include <cuda_bf16.h>

// out[row,m] = ( fp32FWHT_m( sum_d fma-chain x[row,d]*W[m,d] ) * (1/sqrt(128)) > 0 ) ? 1 : 0
//
// Bit-exact vs reference (rel_err == 0.0, R2/R12): one fp32 accumulator per
// output, strictly sequential fmaf over d=0..1023; reference-order fp32 FWHT.
//
// R13: wave balancing. R12's grid=256 at 2 CTA/SM leaves 40 of 148 SMs with a
// single CTA (86.5% chip util, occ 22.1% measured). Re-tile to BM=32 with
// 64-thread CTAs (SAME 8x8 microtile / BK=16 inner loop), grid=1024 at
// 8 CTA/SM -> 136 SMs x 7 + 12 x 6 tiles = 98.9% utilization.
//
// x [32768,1024] fp32, W [128,1024] fp32, out [32768,128] fp32.

#define MOUT 128
#define BM   32
#define BK   16

__global__ void __launch_bounds__(64, 8)
gemm_fwht_sign_kernel(const float* __restrict__ x, const float* __restrict__ W,
                      float* __restrict__ out, int K) {
    // GEMM tiles (As 2KB + Bs 8KB) overlaid with FWHT buffer hb[32][132] (16.9KB)
    __shared__ __align__(16) char smbuf[BM * (MOUT + 4) * 4];   // 16896 B
    float (*As)[BM]       = reinterpret_cast<float(*)[BM]>(smbuf);
    float (*Bs)[MOUT]     = reinterpret_cast<float(*)[MOUT]>(smbuf + BK * BM * 4);
    float (*hb)[MOUT + 4] = reinterpret_cast<float(*)[MOUT + 4]>(smbuf);

    const int tid = threadIdx.x;      // 0..63
    const int tr  = tid >> 4;         // 0..3  -> rows tr*8..+7
    const int tc  = tid & 15;         // 0..15 -> cols tc*8..+7
    const int block_row = blockIdx.x * BM;

    // staging: A = 128 float4 (2/thread), B = 512 float4 (8/thread)
    const int ra = tid >> 2;          // 0..15 (A row, +16 for p=1)
    const int qa = tid & 3;           // k-float4

    const float4* xA0 = (const float4*)(x + (size_t)(block_row + ra) * K) + qa;
    const float4* xA1 = (const float4*)(x + (size_t)(block_row + ra + 16) * K) + qa;
    const float4* wB[8];
#pragma unroll
    for (int p = 0; p < 8; ++p)
        wB[p] = (const float4*)(W + (size_t)(ra + 16 * p) * K) + qa;

    float acc[8][8];
#pragma unroll
    for (int i = 0; i < 8; ++i)
#pragma unroll
        for (int j = 0; j < 8; ++j) acc[i][j] = 0.0f;

    const int nkt = K / BK;           // 64

    float4 pa0 = xA0[0];
    float4 pa1 = xA1[0];
    float4 pb[8];
#pragma unroll
    for (int p = 0; p < 8; ++p) pb[p] = wB[p][0];

    for (int kt = 0; kt < nkt; ++kt) {
        const int kc = qa * 4;
        As[kc + 0][ra] = pa0.x; As[kc + 1][ra] = pa0.y;
        As[kc + 2][ra] = pa0.z; As[kc + 3][ra] = pa0.w;
        As[kc + 0][ra + 16] = pa1.x; As[kc + 1][ra + 16] = pa1.y;
        As[kc + 2][ra + 16] = pa1.z; As[kc + 3][ra + 16] = pa1.w;
#pragma unroll
        for (int p = 0; p < 8; ++p) {
            Bs[kc + 0][ra + 16 * p] = pb[p].x;
            Bs[kc + 1][ra + 16 * p] = pb[p].y;
            Bs[kc + 2][ra + 16 * p] = pb[p].z;
            Bs[kc + 3][ra + 16 * p] = pb[p].w;
        }
        __syncthreads();

        if (kt + 1 < nkt) {
            const int off = (kt + 1) * (BK / 4);
            pa0 = xA0[off]; pa1 = xA1[off];
#pragma unroll
            for (int p = 0; p < 8; ++p) pb[p] = wB[p][off];
        }

        // strictly sequential k accumulation (identical chain to R2/R12)
#pragma unroll
        for (int k = 0; k < BK; ++k) {
            float4 a0 = *(const float4*)&As[k][tr * 8];
            float4 a1 = *(const float4*)&As[k][tr * 8 + 4];
            float4 b0 = *(const float4*)&Bs[k][tc * 8];
            float4 b1 = *(const float4*)&Bs[k][tc * 8 + 4];
            float av[8] = {a0.x, a0.y, a0.z, a0.w, a1.x, a1.y, a1.z, a1.w};
            float bv[8] = {b0.x, b0.y, b0.z, b0.w, b1.x, b1.y, b1.z, b1.w};
#pragma unroll
            for (int i = 0; i < 8; ++i)
#pragma unroll
                for (int j = 0; j < 8; ++j)
                    acc[i][j] = fmaf(av[i], bv[j], acc[i][j]);
        }
        __syncthreads();
    }

    // ---- epilogue: fp32 FWHT along m (reference butterfly order) + sign ----
    const float scale = 0.08838834764831844f;   // fp32( 1/sqrt(128) )

    // dump accumulators (all 32 rows fit the buffer at once)
#pragma unroll
    for (int i = 0; i < 8; ++i)
#pragma unroll
        for (int j = 0; j < 8; ++j)
            hb[tr * 8 + i][tc * 8 + j] = acc[i][j];
    __syncthreads();

    for (int half = 1; half < MOUT; half <<= 1) {
#pragma unroll
        for (int p = 0; p < 32; ++p) {          // 32 rows * 64 pairs / 64 thr
            const int pidx = tid + p * 64;
            const int row = pidx >> 6;
            const int t   = pidx & 63;
            const int j   = ((t & ~(half - 1)) << 1) | (t & (half - 1));
            const float a = hb[row][j];
            const float b = hb[row][j + half];
            hb[row][j]        = a + b;
            hb[row][j + half] = a - b;
        }
        __syncthreads();
    }

#pragma unroll
    for (int p = 0; p < 16; ++p) {              // 32*128 floats = 1024 float4
        const int f4  = tid + p * 64;
        const int row = f4 >> 5;
        const int c   = (f4 & 31) * 4;
        float4 v = *(const float4*)&hb[row][c];
        float4 o;
        o.x = (v.x * scale > 0.0f) ? 1.0f : 0.0f;
        o.y = (v.y * scale > 0.0f) ? 1.0f : 0.0f;
        o.z = (v.z * scale > 0.0f) ? 1.0f : 0.0f;
        o.w = (v.w * scale > 0.0f) ? 1.0f : 0.0f;
        *(float4*)(out + (size_t)(block_row + row) * MOUT + c) = o;
    }
}

extern "C" void kernel_launch(void* const* d_in, const int* in_sizes, int n_in,
                              void* d_out, int out_size) {
    const float* x = (const float*)d_in[0];   // [rows, K]
    const float* W = (const float*)d_in[1];   // [128, K]
    float* out = (float*)d_out;               // [rows, 128]

    const int K = in_sizes[1] / MOUT;         // 1024
    const int rows = in_sizes[0] / K;         // 32768

    gemm_fwht_sign_kernel<<<rows / BM, 64>>>(x, W, out, K);
}

// round 16
// speedup vs baseline: 1.4084x; 1.4084x over previous
#include <cuda_runtime.h>
#include <cstdint>

// out[row,m] = ( fp32FWHT_m( sum_d fma-chain x[row,d]*W[m,d] ) * (1/sqrt(128)) > 0 ) ? 1 : 0
//
// Bit-exact vs reference (rel_err == 0.0, R2/R12): one fp32 accumulator per
// output, strictly sequential fmaf over d=0..1023; reference-order fp32 FWHT.
//
// R14: wave-balanced R12. 64-thread CTAs (BM=32), grid=1024 -> 136 SMs x 7 +
// 12 x 6 (98.9% thread balance vs R12's 86.5%). R13's register blowup fixed:
// W pre-transposed once so the B tile stages via cp.async (zero registers,
// zero STS); A stages exactly as R12 (2 float4 regs). Inner loop = R12's.
//
// x [32768,1024] fp32, W [128,1024] fp32, out [32768,128] fp32.

#define MOUT 128
#define BM   32
#define BK   16
#define K_DIM 1024

__device__ __align__(16) float g_WT[K_DIM * MOUT];   // W transposed: [k][n]

__device__ __forceinline__ uint32_t smem_u32(const void* p) {
    uint32_t a;
    asm("{ .reg .u64 t; cvta.to.shared.u64 t, %1; cvt.u32.u64 %0, t; }"
        : "=r"(a) : "l"(p));
    return a;
}
__device__ __forceinline__ void cpa16(uint32_t dst, const void* src) {
    asm volatile("cp.async.ca.shared.global [%0], [%1], 16;"
                 :: "r"(dst), "l"(src) : "memory");
}

// ---- one-time transpose: W[128][1024] -> g_WT[1024][128] (values verbatim) ----
__global__ void transpose_w_kernel(const float* __restrict__ W) {
    __shared__ float t[32][33];
    const int bk = blockIdx.x;     // 32-wide k slab
    const int bm = blockIdx.y;     // 32-wide m slab
    const int tx = threadIdx.x;    // 0..31
    const int ty = threadIdx.y;    // 0..7
#pragma unroll
    for (int i = 0; i < 32; i += 8)
        t[ty + i][tx] = W[(size_t)(bm * 32 + ty + i) * K_DIM + bk * 32 + tx];
    __syncthreads();
#pragma unroll
    for (int i = 0; i < 32; i += 8)
        g_WT[(size_t)(bk * 32 + ty + i) * MOUT + bm * 32 + tx] = t[tx][ty + i];
}

// ---- main: balanced GEMM + FWHT + sign ----
__global__ void __launch_bounds__(64, 8)
gemm_fwht_sign_kernel(const float* __restrict__ x, float* __restrict__ out) {
    // As[16][32] (2048B) + Bs double buffer (2 x 8192B) = 18432B; FWHT hb
    // (32*132*4 = 16896B) overlays after GEMM.
    __shared__ __align__(16) char smbuf[18432];
    float (*As)[BM] = reinterpret_cast<float(*)[BM]>(smbuf);
    float (*hb)[MOUT + 4] = reinterpret_cast<float(*)[MOUT + 4]>(smbuf);
    const uint32_t bs_base[2] = {smem_u32(smbuf + 2048), smem_u32(smbuf + 10240)};
    float* const bs_ptr[2] = {(float*)(smbuf + 2048), (float*)(smbuf + 10240)};

    const int tid = threadIdx.x;      // 0..63
    const int tr  = tid >> 4;         // 0..3  -> rows tr*8..+7
    const int tc  = tid & 15;         // 0..15 -> cols tc*8..+7
    const int block_row = blockIdx.x * BM;

    const int ra = tid >> 2;          // 0..15 (A staging row; +16 for second)
    const int qa = tid & 3;           // k-float4

    const float4* xA0 = (const float4*)(x + (size_t)(block_row + ra) * K_DIM) + qa;
    const float4* xA1 = (const float4*)(x + (size_t)(block_row + ra + 16) * K_DIM) + qa;

    // B staging: 512 16B chunks per tile, 8 per thread.
    // chunk = tid + i*64 -> k_local = chunk>>5, n = (chunk&31)*4
    const int bkl[8] = {(tid) >> 5, (tid + 64) >> 5, (tid + 128) >> 5, (tid + 192) >> 5,
                        (tid + 256) >> 5, (tid + 320) >> 5, (tid + 384) >> 5, (tid + 448) >> 5};
    const int bnc = (tid & 31) * 4;   // same n for all i (tid&31 invariant under +64)

    float acc[8][8];
#pragma unroll
    for (int i = 0; i < 8; ++i)
#pragma unroll
        for (int j = 0; j < 8; ++j) acc[i][j] = 0.0f;

    const int nkt = K_DIM / BK;       // 64

    // prologue: A(0) -> regs, B(0) -> buf0 via cp.async
    float4 pa0 = xA0[0];
    float4 pa1 = xA1[0];
#pragma unroll
    for (int i = 0; i < 8; ++i)
        cpa16(bs_base[0] + (uint32_t)(bkl[i] * MOUT + bnc) * 4,
              g_WT + (size_t)bkl[i] * MOUT + bnc);
    asm volatile("cp.async.commit_group;" ::: "memory");

    for (int kt = 0; kt < nkt; ++kt) {
        const int buf = kt & 1;
        // STS A(kt): prior compute's As reads finished at last iter's end-sync
        const int kc = qa * 4;
        As[kc + 0][ra] = pa0.x; As[kc + 1][ra] = pa0.y;
        As[kc + 2][ra] = pa0.z; As[kc + 3][ra] = pa0.w;
        As[kc + 0][ra + 16] = pa1.x; As[kc + 1][ra + 16] = pa1.y;
        As[kc + 2][ra + 16] = pa1.z; As[kc + 3][ra + 16] = pa1.w;

        if (kt + 1 < nkt) {
            // B(kt+1) -> other buffer (its readers finished at iter kt-1 end-sync)
            const size_t kb = (size_t)(kt + 1) * BK;
#pragma unroll
            for (int i = 0; i < 8; ++i)
                cpa16(bs_base[buf ^ 1] + (uint32_t)(bkl[i] * MOUT + bnc) * 4,
                      g_WT + (kb + bkl[i]) * MOUT + bnc);
            asm volatile("cp.async.commit_group;" ::: "memory");
            // A(kt+1) -> regs
            const int off = (kt + 1) * (BK / 4);
            pa0 = xA0[off]; pa1 = xA1[off];
            asm volatile("cp.async.wait_group 1;" ::: "memory");   // B(kt) landed
        } else {
            asm volatile("cp.async.wait_group 0;" ::: "memory");
        }
        __syncthreads();

        // strictly sequential k accumulation (identical chain to R2/R12)
        const float* Bs = bs_ptr[buf];
#pragma unroll
        for (int k = 0; k < BK; ++k) {
            float4 a0 = *(const float4*)&As[k][tr * 8];
            float4 a1 = *(const float4*)&As[k][tr * 8 + 4];
            float4 b0 = *(const float4*)&Bs[k * MOUT + tc * 8];
            float4 b1 = *(const float4*)&Bs[k * MOUT + tc * 8 + 4];
            float av[8] = {a0.x, a0.y, a0.z, a0.w, a1.x, a1.y, a1.z, a1.w};
            float bv[8] = {b0.x, b0.y, b0.z, b0.w, b1.x, b1.y, b1.z, b1.w};
#pragma unroll
            for (int i = 0; i < 8; ++i)
#pragma unroll
                for (int j = 0; j < 8; ++j)
                    acc[i][j] = fmaf(av[i], bv[j], acc[i][j]);
        }
        __syncthreads();
    }

    // ---- epilogue: fp32 FWHT along m (reference butterfly order) + sign ----
    const float scale = 0.08838834764831844f;   // fp32( 1/sqrt(128) )

#pragma unroll
    for (int i = 0; i < 8; ++i)
#pragma unroll
        for (int j = 0; j < 8; ++j)
            hb[tr * 8 + i][tc * 8 + j] = acc[i][j];
    __syncthreads();

    for (int half = 1; half < MOUT; half <<= 1) {
#pragma unroll
        for (int p = 0; p < 32; ++p) {          // 32 rows * 64 pairs / 64 thr
            const int pidx = tid + p * 64;
            const int row = pidx >> 6;
            const int t   = pidx & 63;
            const int j   = ((t & ~(half - 1)) << 1) | (t & (half - 1));
            const float a = hb[row][j];
            const float b = hb[row][j + half];
            hb[row][j]        = a + b;
            hb[row][j + half] = a - b;
        }
        __syncthreads();
    }

#pragma unroll
    for (int p = 0; p < 16; ++p) {              // 32*128 floats = 1024 float4
        const int f4  = tid + p * 64;
        const int row = f4 >> 5;
        const int c   = (f4 & 31) * 4;
        float4 v = *(const float4*)&hb[row][c];
        float4 o;
        o.x = (v.x * scale > 0.0f) ? 1.0f : 0.0f;
        o.y = (v.y * scale > 0.0f) ? 1.0f : 0.0f;
        o.z = (v.z * scale > 0.0f) ? 1.0f : 0.0f;
        o.w = (v.w * scale > 0.0f) ? 1.0f : 0.0f;
        *(float4*)(out + (size_t)(block_row + row) * MOUT + c) = o;
    }
}

extern "C" void kernel_launch(void* const* d_in, const int* in_sizes, int n_in,
                              void* d_out, int out_size) {
    const float* x = (const float*)d_in[0];   // [32768, 1024]
    const float* W = (const float*)d_in[1];   // [128, 1024]
    float* out = (float*)d_out;               // [32768, 128]

    transpose_w_kernel<<<dim3(K_DIM / 32, MOUT / 32), dim3(32, 8)>>>(W);
    gemm_fwht_sign_kernel<<<32768 / BM, 64>>>(x, out);
}